// round 12
// baseline (speedup 1.0000x reference)
#include <cuda_runtime.h>
#include <cuda_bf16.h>
#include <math.h>

#define SEQ    2048
#define HID    2048
#define NH     16
#define HD     128
#define BATCH  2
#define WIN    256
#define MTOT   (BATCH*SEQ)

// ---------------- scratch (static device globals; no allocations) -----------
__device__ __nv_bfloat16 g_xhi[MTOT*HID], g_xlo[MTOT*HID];     // split x
__device__ __nv_bfloat16 g_Whi[4ull*HID*HID], g_Wlo[4ull*HID*HID]; // split W (K,N)
__device__ __nv_bfloat16 g_Qhi[BATCH*NH*SEQ*HD], g_Qlo[BATCH*NH*SEQ*HD]; // [B,H,S,D]
__device__ __nv_bfloat16 g_Khi[BATCH*NH*SEQ*HD], g_Klo[BATCH*NH*SEQ*HD];
__device__ __nv_bfloat16 g_Vhi[BATCH*NH*SEQ*HD], g_Vlo[BATCH*NH*SEQ*HD];
__device__ __nv_bfloat16 g_ahi[MTOT*HID], g_alo[MTOT*HID];     // split attn out
__device__ float2 g_rope[SEQ*64];

// ---------------- RoPE table -------------------------------------------------
__global__ void rope_tab_kernel() {
    int idx = blockIdx.x * blockDim.x + threadIdx.x;
    if (idx >= SEQ * 64) return;
    int s = idx >> 6, j = idx & 63;
    float invf = (float)pow(10000.0, -(double)j / 64.0);
    float ang  = (float)s * invf;
    double a   = (double)ang;
    g_rope[idx] = make_float2((float)cos(a), (float)sin(a));
}

// ---------------- fp32 -> bf16 hi/lo split -----------------------------------
__global__ void split_kernel(const float* __restrict__ in,
                             __nv_bfloat16* __restrict__ hi,
                             __nv_bfloat16* __restrict__ lo, int n4) {
    int i = blockIdx.x * blockDim.x + threadIdx.x;
    if (i >= n4) return;
    float4 f = ((const float4*)in)[i];
    float v[4] = {f.x, f.y, f.z, f.w};
    unsigned h[2], l[2];
    #pragma unroll
    for (int p = 0; p < 2; p++) {
        __nv_bfloat16 h0 = __float2bfloat16(v[2*p]);
        __nv_bfloat16 h1 = __float2bfloat16(v[2*p+1]);
        __nv_bfloat16 l0 = __float2bfloat16(v[2*p]   - __bfloat162float(h0));
        __nv_bfloat16 l1 = __float2bfloat16(v[2*p+1] - __bfloat162float(h1));
        __nv_bfloat162 hh = __halves2bfloat162(h0, h1);
        __nv_bfloat162 ll = __halves2bfloat162(l0, l1);
        h[p] = *(unsigned*)&hh; l[p] = *(unsigned*)&ll;
    }
    *(uint2*)(hi + 4 * (size_t)i) = make_uint2(h[0], h[1]);
    *(uint2*)(lo + 4 * (size_t)i) = make_uint2(l[0], l[1]);
}

// ---------------- helpers ----------------------------------------------------
__device__ __forceinline__ unsigned smem_u32(const void* p) {
    return (unsigned)__cvta_generic_to_shared(p);
}
__device__ __forceinline__ void ldsm_x4(unsigned &r0, unsigned &r1,
                                        unsigned &r2, unsigned &r3, unsigned a) {
    asm volatile("ldmatrix.sync.aligned.m8n8.x4.shared.b16 {%0,%1,%2,%3},[%4];"
                 : "=r"(r0), "=r"(r1), "=r"(r2), "=r"(r3) : "r"(a));
}
__device__ __forceinline__ void ldsm_x4_t(unsigned &r0, unsigned &r1,
                                          unsigned &r2, unsigned &r3, unsigned a) {
    asm volatile("ldmatrix.sync.aligned.m8n8.x4.trans.shared.b16 {%0,%1,%2,%3},[%4];"
                 : "=r"(r0), "=r"(r1), "=r"(r2), "=r"(r3) : "r"(a));
}
__device__ __forceinline__ void mma16816(float* c, const unsigned* a, const unsigned* b) {
    asm volatile(
        "mma.sync.aligned.m16n8k16.row.col.f32.bf16.bf16.f32 "
        "{%0,%1,%2,%3},{%4,%5,%6,%7},{%8,%9},{%0,%1,%2,%3};"
        : "+f"(c[0]), "+f"(c[1]), "+f"(c[2]), "+f"(c[3])
        : "r"(a[0]), "r"(a[1]), "r"(a[2]), "r"(a[3]), "r"(b[0]), "r"(b[1]));
}
__device__ __forceinline__ void cp16(unsigned s, const void* g) {
    asm volatile("cp.async.cg.shared.global [%0], [%1], 16;" :: "r"(s), "l"(g));
}
__device__ __forceinline__ void cp_commit() { asm volatile("cp.async.commit_group;"); }
__device__ __forceinline__ void cp_wait1()  { asm volatile("cp.async.wait_group 1;"); }
__device__ __forceinline__ void cp_wait0()  { asm volatile("cp.async.wait_group 0;"); }

__device__ __forceinline__ void pack_split(unsigned &h, unsigned &l, float v0, float v1) {
    __nv_bfloat16 h0 = __float2bfloat16(v0), h1 = __float2bfloat16(v1);
    __nv_bfloat16 l0 = __float2bfloat16(v0 - __bfloat162float(h0));
    __nv_bfloat16 l1 = __float2bfloat16(v1 - __bfloat162float(h1));
    __nv_bfloat162 hh = __halves2bfloat162(h0, h1), ll = __halves2bfloat162(l0, l1);
    h = *(unsigned*)&hh; l = *(unsigned*)&ll;
}
__device__ __forceinline__ void split2_store(__nv_bfloat16* hp, __nv_bfloat16* lp,
                                             float v0, float v1) {
    unsigned h, l;
    pack_split(h, l, v0, v1);
    *(unsigned*)hp = h; *(unsigned*)lp = l;
}

// ---------------- GEMM geometry ----------------------------------------------
#define ASTR 40
#define BSTR 136
#define STAGES 3
#define A_ONE   (256*ASTR)
#define A_STAGE (2*A_ONE)
#define B_ONE   (32*BSTR)
#define B_STAGE (2*B_ONE)
#define B_BASE  (STAGES*A_STAGE)
#define GEMM_SMEM_BF16 (B_BASE + STAGES*B_STAGE)
#define GEMM_SMEM_BYTES (GEMM_SMEM_BF16*2)

__device__ __forceinline__ void tc_mainloop(
    const __nv_bfloat16* __restrict__ Ahi_g, const __nv_bfloat16* __restrict__ Alo_g,
    const __nv_bfloat16* __restrict__ Bhi_g, const __nv_bfloat16* __restrict__ Blo_g,
    int m0, int n0, __nv_bfloat16* sm, float acc[4][8][4])
{
    const int tid = threadIdx.x;
    const int lane = tid & 31, wid = tid >> 5;
    const int warp_m = wid >> 1, warp_n = wid & 1;
    const unsigned smB = smem_u32(sm);

    const int NT = HID / 32;

    auto issue = [&](int slot, int kt) {
        unsigned sa = smB + (slot * A_STAGE) * 2;
        unsigned sb = smB + (B_BASE + slot * B_STAGE) * 2;
        const __nv_bfloat16* Ah = Ahi_g + (size_t)m0 * HID + kt * 32;
        const __nv_bfloat16* Al = Alo_g + (size_t)m0 * HID + kt * 32;
        const __nv_bfloat16* Bh = Bhi_g + (size_t)(kt * 32) * HID + n0;
        const __nv_bfloat16* Bl = Blo_g + (size_t)(kt * 32) * HID + n0;
        #pragma unroll
        for (int i = 0; i < 4; i++) {
            int id = tid + i * 256;
            int r = id >> 2, c8 = (id & 3) * 8;
            cp16(sa + (r * ASTR + c8) * 2,         Ah + (size_t)r * HID + c8);
            cp16(sa + (A_ONE + r * ASTR + c8) * 2, Al + (size_t)r * HID + c8);
        }
        #pragma unroll
        for (int i = 0; i < 2; i++) {
            int id = tid + i * 256;
            int r = id >> 4, c8 = (id & 15) * 8;
            cp16(sb + (r * BSTR + c8) * 2,         Bh + (size_t)r * HID + c8);
            cp16(sb + (B_ONE + r * BSTR + c8) * 2, Bl + (size_t)r * HID + c8);
        }
    };

    const int arow  = warp_m * 64 + (lane & 15);
    const int acol8 = (lane >> 4) * 8;
    const int brow  = lane & 15;
    const int bcol  = warp_n * 32 + (lane >> 4) * 8;

    #pragma unroll
    for (int s = 0; s < STAGES - 1; s++) { issue(s, s); cp_commit(); }

    for (int kt = 0; kt < NT; kt++) {
        cp_wait1();
        __syncthreads();
        if (kt + STAGES - 1 < NT) issue((kt + STAGES - 1) % STAGES, kt + STAGES - 1);
        cp_commit();

        const int slot = kt % STAGES;
        unsigned aHiB = smB + (slot * A_STAGE) * 2;
        unsigned aLoB = aHiB + A_ONE * 2;
        unsigned bHiB = smB + (B_BASE + slot * B_STAGE) * 2;
        unsigned bLoB = bHiB + B_ONE * 2;

        #pragma unroll
        for (int kb = 0; kb < 32; kb += 16) {
            unsigned bh[8][2], bl[8][2];
            #pragma unroll
            for (int p = 0; p < 4; p++) {
                int nOff = (p & 1) * 16 + (p >> 1) * 64;
                unsigned off = (unsigned)(((kb + brow) * BSTR + bcol + nOff) * 2);
                unsigned r0, r1, r2, r3;
                ldsm_x4_t(r0, r1, r2, r3, bHiB + off);
                bh[2*p][0] = r0; bh[2*p][1] = r1; bh[2*p+1][0] = r2; bh[2*p+1][1] = r3;
                ldsm_x4_t(r0, r1, r2, r3, bLoB + off);
                bl[2*p][0] = r0; bl[2*p][1] = r1; bl[2*p+1][0] = r2; bl[2*p+1][1] = r3;
            }
            #pragma unroll
            for (int i = 0; i < 4; i++) {
                unsigned ah[4], al[4];
                unsigned off = (unsigned)(((arow + 16 * i) * ASTR + kb + acol8) * 2);
                ldsm_x4(ah[0], ah[1], ah[2], ah[3], aHiB + off);
                ldsm_x4(al[0], al[1], al[2], al[3], aLoB + off);
                // pass-major: 8 independent accumulator chains between deps
                #pragma unroll
                for (int j = 0; j < 8; j++) mma16816(acc[i][j], ah, bh[j]);
                #pragma unroll
                for (int j = 0; j < 8; j++) mma16816(acc[i][j], ah, bl[j]);
                #pragma unroll
                for (int j = 0; j < 8; j++) mma16816(acc[i][j], al, bh[j]);
            }
        }
        __syncthreads();
    }
}

// ---------------- fused QKV GEMM (+bias, +RoPE, bf16 hi/lo BHSD epilogue) ----
__global__ __launch_bounds__(256, 1) void qkv_tc_kernel(
    const float* __restrict__ bQ, const float* __restrict__ bK,
    const float* __restrict__ bV)
{
    extern __shared__ __align__(16) __nv_bfloat16 smg[];
    const int z = blockIdx.z;
    const float* bias = (z == 0) ? bQ : ((z == 1) ? bK : bV);
    const int m0 = blockIdx.y * 256, n0 = blockIdx.x * 128;

    float acc[4][8][4];
    #pragma unroll
    for (int i = 0; i < 4; i++)
        #pragma unroll
        for (int j = 0; j < 8; j++)
            #pragma unroll
            for (int r = 0; r < 4; r++) acc[i][j][r] = 0.f;

    const size_t wz = (size_t)z * HID * HID;
    tc_mainloop(g_xhi, g_xlo, g_Whi + wz, g_Wlo + wz, m0, n0, smg, acc);

    const int tid = threadIdx.x, lane = tid & 31, wid = tid >> 5;
    const int warp_m = wid >> 1, warp_n = wid & 1;
    const int g = lane >> 2, c = lane & 3;
    const int wb = warp_n * 32;
    const int h = blockIdx.x;
    __nv_bfloat16 *oh, *ol;
    if (z == 0)      { oh = g_Qhi; ol = g_Qlo; }
    else if (z == 1) { oh = g_Khi; ol = g_Klo; }
    else             { oh = g_Vhi; ol = g_Vlo; }

    #pragma unroll
    for (int i = 0; i < 4; i++) {
        #pragma unroll
        for (int rh = 0; rh < 2; rh++) {
            int rm = m0 + warp_m * 64 + 16 * i + g + 8 * rh;
            int bb = rm >> 11, s = rm & (SEQ - 1);
            size_t ro = ((size_t)(bb * NH + h) * SEQ + s) * HD;
            if (z < 2) {
                #pragma unroll
                for (int j = 0; j < 4; j++) {
                    int d1 = wb + 8 * j + 2 * c;
                    float t1[2], t2[2];
                    #pragma unroll
                    for (int d = 0; d < 2; d++) {
                        int reg = rh * 2 + d;
                        float a1 = acc[i][j][reg]     + bias[n0 + d1 + d];
                        float a2 = acc[i][j + 4][reg] + bias[n0 + d1 + 64 + d];
                        float2 cs = g_rope[s * 64 + d1 + d];
                        t1[d] = a1 * cs.x - a2 * cs.y;
                        t2[d] = a1 * cs.y + a2 * cs.x;
                    }
                    split2_store(oh + ro + d1,      ol + ro + d1,      t1[0], t1[1]);
                    split2_store(oh + ro + d1 + 64, ol + ro + d1 + 64, t2[0], t2[1]);
                }
            } else {
                #pragma unroll
                for (int j = 0; j < 8; j++) {
                    int col = wb + (j & 3) * 8 + (j >> 2) * 64 + 2 * c;
                    float v0 = acc[i][j][rh * 2]     + bias[n0 + col];
                    float v1 = acc[i][j][rh * 2 + 1] + bias[n0 + col + 1];
                    split2_store(oh + ro + col, ol + ro + col, v0, v1);
                }
            }
        }
    }
}

// ---------------- output projection GEMM (+bias) ----------------------------
__global__ __launch_bounds__(256, 1) void out_tc_kernel(
    const float* __restrict__ bO, float* __restrict__ out)
{
    extern __shared__ __align__(16) __nv_bfloat16 smg[];
    const int m0 = blockIdx.y * 256, n0 = blockIdx.x * 128;

    float acc[4][8][4];
    #pragma unroll
    for (int i = 0; i < 4; i++)
        #pragma unroll
        for (int j = 0; j < 8; j++)
            #pragma unroll
            for (int r = 0; r < 4; r++) acc[i][j][r] = 0.f;

    const size_t wz = (size_t)3 * HID * HID;
    tc_mainloop(g_ahi, g_alo, g_Whi + wz, g_Wlo + wz, m0, n0, smg, acc);

    const int tid = threadIdx.x, lane = tid & 31, wid = tid >> 5;
    const int warp_m = wid >> 1, warp_n = wid & 1;
    const int g = lane >> 2, c = lane & 3;
    const int wb = warp_n * 32;

    #pragma unroll
    for (int i = 0; i < 4; i++) {
        #pragma unroll
        for (int rh = 0; rh < 2; rh++) {
            int rm = m0 + warp_m * 64 + 16 * i + g + 8 * rh;
            #pragma unroll
            for (int j = 0; j < 8; j++) {
                #pragma unroll
                for (int d = 0; d < 2; d++) {
                    int col = n0 + wb + (j & 3) * 8 + (j >> 2) * 64 + 2 * c + d;
                    out[(size_t)rm * HID + col] = acc[i][j][rh * 2 + d] + bO[col];
                }
            }
        }
    }
}

// ---------------- tensor-core sliding-window flash attention -----------------
// block = 128 q-rows x (b,h); 8 warps x 16 q-rows; k-tiles of 64 keys.
#define AQH 0
#define AQL 17408
#define AKH 34816
#define AKL 43520
#define AVH 52224
#define AVL 60928
#define ATT_SMEM_BYTES (69632*2)

__global__ __launch_bounds__(256, 1) void attn_tc_kernel(const float* __restrict__ kw) {
    extern __shared__ __align__(16) __nv_bfloat16 smA[];
    const unsigned smB = smem_u32(smA);
    const int tid = threadIdx.x, lane = tid & 31, wid = tid >> 5;
    const int q0 = blockIdx.x * 128, h = blockIdx.y, b = blockIdx.z;
    const size_t base = (size_t)(b * NH + h) * SEQ * HD;
    const int kstart = (q0 >= WIN) ? (q0 - WIN) : 0;
    const int ntile = (q0 + 128 - kstart) >> 6;

    {   // Q tile 128x128 hi+lo -> smem
        const char* qh = (const char*)(g_Qhi + base + (size_t)q0 * HD);
        const char* ql = (const char*)(g_Qlo + base + (size_t)q0 * HD);
        #pragma unroll
        for (int i = 0; i < 8; i++) {
            int id = tid + i * 256;
            int r = id >> 4, cb = (id & 15) * 16;
            cp16(smB + AQH * 2 + r * 272 + cb, qh + r * 256 + cb);
            cp16(smB + AQL * 2 + r * 272 + cb, ql + r * 256 + cb);
        }
        cp_commit();
    }

    const float mult = 0.08838834764831845f * kw[h];
    const int qlo = q0 + wid * 16;
    const int r4 = lane >> 2, c2 = (lane & 3) * 2;
    const int qiA = qlo + r4, qiB = qiA + 8;

    float O[16][4];
    #pragma unroll
    for (int dt = 0; dt < 16; dt++) { O[dt][0]=O[dt][1]=O[dt][2]=O[dt][3]=0.f; }
    float mA = -3e38f, mB = -3e38f, lA = 0.f, lB = 0.f;

    for (int kt = 0; kt < ntile; kt++) {
        const int k0 = kstart + kt * 64;
        __syncthreads();                       // prev tile fully consumed
        {
            const char* kh = (const char*)(g_Khi + base + (size_t)k0 * HD);
            const char* kl = (const char*)(g_Klo + base + (size_t)k0 * HD);
            const char* vh = (const char*)(g_Vhi + base + (size_t)k0 * HD);
            const char* vl = (const char*)(g_Vlo + base + (size_t)k0 * HD);
            #pragma unroll
            for (int i = 0; i < 4; i++) {
                int id = tid + i * 256;
                int r = id >> 4, cb = (id & 15) * 16;
                cp16(smB + AKH * 2 + r * 272 + cb, kh + r * 256 + cb);
                cp16(smB + AKL * 2 + r * 272 + cb, kl + r * 256 + cb);
                cp16(smB + AVH * 2 + r * 272 + cb, vh + r * 256 + cb);
                cp16(smB + AVL * 2 + r * 272 + cb, vl + r * 256 + cb);
            }
            cp_commit();
            cp_wait0();
        }
        __syncthreads();

        int tmn = (qlo - WIN - k0) >> 3; if (tmn < 0) tmn = 0;
        int tmx = (qlo + 15 - k0) >> 3; if (tmx > 7) tmx = 7;
        if (tmn > tmx) continue;               // whole tile out of this warp's window

        // ---- S = Q K^T (split-bf16, 3 passes) ----
        float S[8][4];
        #pragma unroll
        for (int t = 0; t < 8; t++) { S[t][0]=S[t][1]=S[t][2]=S[t][3]=0.f; }

        #pragma unroll
        for (int kc = 0; kc < 8; kc++) {
            unsigned qh[4], ql2[4];
            unsigned qoff = (unsigned)(((wid * 16 + (lane & 15)) * 136 + kc * 16 + (lane >> 4) * 8) * 2);
            ldsm_x4(qh[0], qh[1], qh[2], qh[3], smB + AQH * 2 + qoff);
            ldsm_x4(ql2[0], ql2[1], ql2[2], ql2[3], smB + AQL * 2 + qoff);
            #pragma unroll
            for (int tp = 0; tp < 4; tp++) {
                if (2 * tp + 1 < tmn || 2 * tp > tmx) continue;
                unsigned koff = (unsigned)(((tp * 16 + (lane & 7) + (lane >> 4) * 8) * 136
                                            + kc * 16 + ((lane >> 3) & 1) * 8) * 2);
                unsigned kh[4], kl2[4];
                ldsm_x4(kh[0], kh[1], kh[2], kh[3], smB + AKH * 2 + koff);
                ldsm_x4(kl2[0], kl2[1], kl2[2], kl2[3], smB + AKL * 2 + koff);
                unsigned bh0[2] = {kh[0], kh[1]},  bh1[2] = {kh[2], kh[3]};
                unsigned bl0[2] = {kl2[0], kl2[1]}, bl1[2] = {kl2[2], kl2[3]};
                mma16816(S[2 * tp],     qh,  bh0);
                mma16816(S[2 * tp + 1], qh,  bh1);
                mma16816(S[2 * tp],     qh,  bl0);
                mma16816(S[2 * tp + 1], qh,  bl1);
                mma16816(S[2 * tp],     ql2, bh0);
                mma16816(S[2 * tp + 1], ql2, bh1);
            }
        }

        // ---- online softmax on fragments ----
        float mlA = -3e38f, mlB = -3e38f;
        #pragma unroll
        for (int t = 0; t < 8; t++) {
            if (t < tmn || t > tmx) continue;
            #pragma unroll
            for (int e = 0; e < 2; e++) {
                int kc2 = k0 + 8 * t + c2 + e;
                float sA = S[t][e] * mult;
                sA = (kc2 <= qiA && kc2 + WIN >= qiA) ? sA : -3e38f;
                S[t][e] = sA; mlA = fmaxf(mlA, sA);
                float sB = S[t][2 + e] * mult;
                sB = (kc2 <= qiB && kc2 + WIN >= qiB) ? sB : -3e38f;
                S[t][2 + e] = sB; mlB = fmaxf(mlB, sB);
            }
        }
        mlA = fmaxf(mlA, __shfl_xor_sync(0xffffffffu, mlA, 1));
        mlA = fmaxf(mlA, __shfl_xor_sync(0xffffffffu, mlA, 2));
        mlB = fmaxf(mlB, __shfl_xor_sync(0xffffffffu, mlB, 1));
        mlB = fmaxf(mlB, __shfl_xor_sync(0xffffffffu, mlB, 2));
        float mnA = fmaxf(mA, mlA), mnB = fmaxf(mB, mlB);
        float cA = __expf(mA - mnA), cB = __expf(mB - mnB);
        float sumA = 0.f, sumB = 0.f;
        #pragma unroll
        for (int t = 0; t < 8; t++) {
            if (t < tmn || t > tmx) { S[t][0]=S[t][1]=S[t][2]=S[t][3]=0.f; continue; }
            float p0 = __expf(S[t][0] - mnA), p1 = __expf(S[t][1] - mnA);
            float p2 = __expf(S[t][2] - mnB), p3 = __expf(S[t][3] - mnB);
            S[t][0] = p0; S[t][1] = p1; S[t][2] = p2; S[t][3] = p3;
            sumA += p0 + p1; sumB += p2 + p3;
        }
        sumA += __shfl_xor_sync(0xffffffffu, sumA, 1);
        sumA += __shfl_xor_sync(0xffffffffu, sumA, 2);
        sumB += __shfl_xor_sync(0xffffffffu, sumB, 1);
        sumB += __shfl_xor_sync(0xffffffffu, sumB, 2);
        lA = lA * cA + sumA; lB = lB * cB + sumB; mA = mnA; mB = mnB;
        #pragma unroll
        for (int dt = 0; dt < 16; dt++) {
            O[dt][0] *= cA; O[dt][1] *= cA; O[dt][2] *= cB; O[dt][3] *= cB;
        }

        // ---- O += P V (split-bf16, 3 passes; P frags from S in-register) ----
        #pragma unroll
        for (int kc = 0; kc < 4; kc++) {
            if (2 * kc + 1 < tmn || 2 * kc > tmx) continue;
            unsigned ph[4], pl[4];
            pack_split(ph[0], pl[0], S[2 * kc][0],     S[2 * kc][1]);
            pack_split(ph[1], pl[1], S[2 * kc][2],     S[2 * kc][3]);
            pack_split(ph[2], pl[2], S[2 * kc + 1][0], S[2 * kc + 1][1]);
            pack_split(ph[3], pl[3], S[2 * kc + 1][2], S[2 * kc + 1][3]);
            #pragma unroll
            for (int dp = 0; dp < 8; dp++) {
                unsigned voff = (unsigned)(((kc * 16 + (lane & 15)) * 136
                                            + dp * 16 + (lane >> 4) * 8) * 2);
                unsigned vh[4], vl2[4];
                ldsm_x4_t(vh[0], vh[1], vh[2], vh[3], smB + AVH * 2 + voff);
                ldsm_x4_t(vl2[0], vl2[1], vl2[2], vl2[3], smB + AVL * 2 + voff);
                unsigned b0h[2] = {vh[0], vh[1]},  b1h[2] = {vh[2], vh[3]};
                unsigned b0l[2] = {vl2[0], vl2[1]}, b1l[2] = {vl2[2], vl2[3]};
                mma16816(O[2 * dp],     ph, b0h);
                mma16816(O[2 * dp + 1], ph, b1h);
                mma16816(O[2 * dp],     ph, b0l);
                mma16816(O[2 * dp + 1], ph, b1l);
                mma16816(O[2 * dp],     pl, b0h);
                mma16816(O[2 * dp + 1], pl, b1h);
            }
        }
    }

    // ---- epilogue: divide by l, split to bf16 hi/lo for the out GEMM ----
    float iA = 1.f / lA, iB = 1.f / lB;
    size_t rowA = ((size_t)b * SEQ + qiA) * HID + h * HD;
    size_t rowB = ((size_t)b * SEQ + qiB) * HID + h * HD;
    #pragma unroll
    for (int dt = 0; dt < 16; dt++) {
        int col = 8 * dt + c2;
        split2_store(g_ahi + rowA + col, g_alo + rowA + col, O[dt][0] * iA, O[dt][1] * iA);
        split2_store(g_ahi + rowB + col, g_alo + rowB + col, O[dt][2] * iB, O[dt][3] * iB);
    }
}

// ---------------- launch -----------------------------------------------------
extern "C" void kernel_launch(void* const* d_in, const int* in_sizes, int n_in,
                              void* d_out, int out_size) {
    const float* x  = (const float*)d_in[0];
    const float* WQ = (const float*)d_in[1];
    const float* bQ = (const float*)d_in[2];
    const float* WK = (const float*)d_in[3];
    const float* bK = (const float*)d_in[4];
    const float* WV = (const float*)d_in[5];
    const float* bV = (const float*)d_in[6];
    const float* WO = (const float*)d_in[7];
    const float* bO = (const float*)d_in[8];
    const float* kw = (const float*)d_in[9];
    float* out = (float*)d_out;

    static __nv_bfloat16 *xhi = nullptr, *xlo = nullptr, *whi = nullptr, *wlo = nullptr;
    static bool attr_set = false;
    if (!xhi) {
        cudaGetSymbolAddress((void**)&xhi, g_xhi);
        cudaGetSymbolAddress((void**)&xlo, g_xlo);
        cudaGetSymbolAddress((void**)&whi, g_Whi);
        cudaGetSymbolAddress((void**)&wlo, g_Wlo);
    }
    if (!attr_set) {
        cudaFuncSetAttribute(qkv_tc_kernel,  cudaFuncAttributeMaxDynamicSharedMemorySize, GEMM_SMEM_BYTES);
        cudaFuncSetAttribute(out_tc_kernel,  cudaFuncAttributeMaxDynamicSharedMemorySize, GEMM_SMEM_BYTES);
        cudaFuncSetAttribute(attn_tc_kernel, cudaFuncAttributeMaxDynamicSharedMemorySize, ATT_SMEM_BYTES);
        attr_set = true;
    }

    rope_tab_kernel<<<(SEQ * 64 + 255) / 256, 256>>>();

    const int n4x = MTOT * HID / 4;
    const int n4w = HID * HID / 4;
    split_kernel<<<(n4x + 255) / 256, 256>>>(x,  xhi, xlo, n4x);
    split_kernel<<<(n4w + 255) / 256, 256>>>(WQ, whi + 0ull * HID * HID, wlo + 0ull * HID * HID, n4w);
    split_kernel<<<(n4w + 255) / 256, 256>>>(WK, whi + 1ull * HID * HID, wlo + 1ull * HID * HID, n4w);
    split_kernel<<<(n4w + 255) / 256, 256>>>(WV, whi + 2ull * HID * HID, wlo + 2ull * HID * HID, n4w);
    split_kernel<<<(n4w + 255) / 256, 256>>>(WO, whi + 3ull * HID * HID, wlo + 3ull * HID * HID, n4w);

    dim3 gq(NH, MTOT / 256, 3);
    qkv_tc_kernel<<<gq, 256, GEMM_SMEM_BYTES>>>(bQ, bK, bV);

    attn_tc_kernel<<<dim3(SEQ / 128, NH, BATCH), 256, ATT_SMEM_BYTES>>>(kw);

    out_tc_kernel<<<dim3(HID / 128, MTOT / 256), 256, GEMM_SMEM_BYTES>>>(bO, out);
}

// round 14
// speedup vs baseline: 1.3855x; 1.3855x over previous
#include <cuda_runtime.h>
#include <cuda_bf16.h>
#include <math.h>

#define SEQ    2048
#define HID    2048
#define NH     16
#define HD     128
#define BATCH  2
#define WIN    256
#define MTOT   (BATCH*SEQ)

// ---------------- scratch (static device globals; no allocations) -----------
__device__ float  g_Q[BATCH*NH*SEQ*HD];      // [B,H,S,D]
__device__ float  g_K[BATCH*NH*SEQ*HD];
__device__ float  g_V[BATCH*NH*SEQ*HD];
__device__ __nv_bfloat16 g_xhi[MTOT*HID], g_xlo[MTOT*HID];     // split x
__device__ __nv_bfloat16 g_Whi[4ull*HID*HID], g_Wlo[4ull*HID*HID]; // split W (K,N)
__device__ __nv_bfloat16 g_ahi[MTOT*HID], g_alo[MTOT*HID];     // split attn out
__device__ float2 g_rope[SEQ*64];

// ---------------- RoPE table -------------------------------------------------
__global__ void rope_tab_kernel() {
    int idx = blockIdx.x * blockDim.x + threadIdx.x;
    if (idx >= SEQ * 64) return;
    int s = idx >> 6, j = idx & 63;
    float invf = (float)pow(10000.0, -(double)j / 64.0);
    float ang  = (float)s * invf;
    double a   = (double)ang;
    g_rope[idx] = make_float2((float)cos(a), (float)sin(a));
}

// ---------------- fp32 -> bf16 hi/lo split -----------------------------------
__global__ void split_kernel(const float* __restrict__ in,
                             __nv_bfloat16* __restrict__ hi,
                             __nv_bfloat16* __restrict__ lo, int n4) {
    int i = blockIdx.x * blockDim.x + threadIdx.x;
    if (i >= n4) return;
    float4 f = ((const float4*)in)[i];
    float v[4] = {f.x, f.y, f.z, f.w};
    unsigned h[2], l[2];
    #pragma unroll
    for (int p = 0; p < 2; p++) {
        __nv_bfloat16 h0 = __float2bfloat16(v[2*p]);
        __nv_bfloat16 h1 = __float2bfloat16(v[2*p+1]);
        __nv_bfloat16 l0 = __float2bfloat16(v[2*p]   - __bfloat162float(h0));
        __nv_bfloat16 l1 = __float2bfloat16(v[2*p+1] - __bfloat162float(h1));
        __nv_bfloat162 hh = __halves2bfloat162(h0, h1);
        __nv_bfloat162 ll = __halves2bfloat162(l0, l1);
        h[p] = *(unsigned*)&hh; l[p] = *(unsigned*)&ll;
    }
    *(uint2*)(hi + 4 * (size_t)i) = make_uint2(h[0], h[1]);
    *(uint2*)(lo + 4 * (size_t)i) = make_uint2(l[0], l[1]);
}

// ---------------- tensor-core helpers ---------------------------------------
__device__ __forceinline__ unsigned smem_u32(const void* p) {
    return (unsigned)__cvta_generic_to_shared(p);
}
__device__ __forceinline__ void ldsm_x4(unsigned &r0, unsigned &r1,
                                        unsigned &r2, unsigned &r3, unsigned a) {
    asm volatile("ldmatrix.sync.aligned.m8n8.x4.shared.b16 {%0,%1,%2,%3},[%4];"
                 : "=r"(r0), "=r"(r1), "=r"(r2), "=r"(r3) : "r"(a));
}
__device__ __forceinline__ void ldsm_x4_t(unsigned &r0, unsigned &r1,
                                          unsigned &r2, unsigned &r3, unsigned a) {
    asm volatile("ldmatrix.sync.aligned.m8n8.x4.trans.shared.b16 {%0,%1,%2,%3},[%4];"
                 : "=r"(r0), "=r"(r1), "=r"(r2), "=r"(r3) : "r"(a));
}
__device__ __forceinline__ void mma16816(float* c, const unsigned* a, const unsigned* b) {
    asm volatile(
        "mma.sync.aligned.m16n8k16.row.col.f32.bf16.bf16.f32 "
        "{%0,%1,%2,%3},{%4,%5,%6,%7},{%8,%9},{%0,%1,%2,%3};"
        : "+f"(c[0]), "+f"(c[1]), "+f"(c[2]), "+f"(c[3])
        : "r"(a[0]), "r"(a[1]), "r"(a[2]), "r"(a[3]), "r"(b[0]), "r"(b[1]));
}
__device__ __forceinline__ void cp16(unsigned s, const void* g) {
    asm volatile("cp.async.cg.shared.global [%0], [%1], 16;" :: "r"(s), "l"(g));
}
__device__ __forceinline__ void cp_commit() { asm volatile("cp.async.commit_group;"); }
__device__ __forceinline__ void cp_wait1()  { asm volatile("cp.async.wait_group 1;"); }

// smem geometry (bf16 units); conflict-free for LDSM / LDSM.T
#define ASTR 40                 // 256 rows x 32 k, 80B rows
#define BSTR 136                // 32 k-rows x 128 n, 272B rows
#define STAGES 3
#define A_ONE   (256*ASTR)
#define A_STAGE (2*A_ONE)
#define B_ONE   (32*BSTR)
#define B_STAGE (2*B_ONE)
#define B_BASE  (STAGES*A_STAGE)
#define GEMM_SMEM_BF16 (B_BASE + STAGES*B_STAGE)
#define GEMM_SMEM_BYTES (GEMM_SMEM_BF16*2)   // 175104

// C[256x128] = A[256xK] * B[Kx128]; split-bf16 3-pass, fp32 accumulate.
// 8 warps: 4 m-warps x 2 n-warps; warp tile 64x64, n interleave
// {0,8,16,24}∪{64,72,80,88} + warp_n*32 so RoPE pairs stay in-thread.
__device__ __forceinline__ void tc_mainloop(
    const __nv_bfloat16* __restrict__ Ahi_g, const __nv_bfloat16* __restrict__ Alo_g,
    const __nv_bfloat16* __restrict__ Bhi_g, const __nv_bfloat16* __restrict__ Blo_g,
    int m0, int n0, __nv_bfloat16* sm, float acc[4][8][4])
{
    const int tid = threadIdx.x;
    const int lane = tid & 31, wid = tid >> 5;
    const int warp_m = wid >> 1, warp_n = wid & 1;
    const unsigned smB = smem_u32(sm);

    const int NT = HID / 32;

    auto issue = [&](int slot, int kt) {
        unsigned sa = smB + (slot * A_STAGE) * 2;
        unsigned sb = smB + (B_BASE + slot * B_STAGE) * 2;
        const __nv_bfloat16* Ah = Ahi_g + (size_t)m0 * HID + kt * 32;
        const __nv_bfloat16* Al = Alo_g + (size_t)m0 * HID + kt * 32;
        const __nv_bfloat16* Bh = Bhi_g + (size_t)(kt * 32) * HID + n0;
        const __nv_bfloat16* Bl = Blo_g + (size_t)(kt * 32) * HID + n0;
        #pragma unroll
        for (int i = 0; i < 4; i++) {               // A: 4 chunks per matrix
            int id = tid + i * 256;
            int r = id >> 2, c8 = (id & 3) * 8;
            cp16(sa + (r * ASTR + c8) * 2,         Ah + (size_t)r * HID + c8);
            cp16(sa + (A_ONE + r * ASTR + c8) * 2, Al + (size_t)r * HID + c8);
        }
        #pragma unroll
        for (int i = 0; i < 2; i++) {               // B: 2 chunks per matrix
            int id = tid + i * 256;
            int r = id >> 4, c8 = (id & 15) * 8;
            cp16(sb + (r * BSTR + c8) * 2,         Bh + (size_t)r * HID + c8);
            cp16(sb + (B_ONE + r * BSTR + c8) * 2, Bl + (size_t)r * HID + c8);
        }
    };

    const int arow  = warp_m * 64 + (lane & 15);
    const int acol8 = (lane >> 4) * 8;
    const int brow  = lane & 15;
    const int bcol  = warp_n * 32 + (lane >> 4) * 8;

    #pragma unroll
    for (int s = 0; s < STAGES - 1; s++) { issue(s, s); cp_commit(); }

    for (int kt = 0; kt < NT; kt++) {
        cp_wait1();
        __syncthreads();
        if (kt + STAGES - 1 < NT) issue((kt + STAGES - 1) % STAGES, kt + STAGES - 1);
        cp_commit();

        const int slot = kt % STAGES;
        unsigned aHiB = smB + (slot * A_STAGE) * 2;
        unsigned aLoB = aHiB + A_ONE * 2;
        unsigned bHiB = smB + (B_BASE + slot * B_STAGE) * 2;
        unsigned bLoB = bHiB + B_ONE * 2;

        #pragma unroll
        for (int kb = 0; kb < 32; kb += 16) {
            unsigned bh[8][2], bl[8][2];
            #pragma unroll
            for (int p = 0; p < 4; p++) {
                int nOff = (p & 1) * 16 + (p >> 1) * 64;
                unsigned off = (unsigned)(((kb + brow) * BSTR + bcol + nOff) * 2);
                unsigned r0, r1, r2, r3;
                ldsm_x4_t(r0, r1, r2, r3, bHiB + off);
                bh[2*p][0] = r0; bh[2*p][1] = r1; bh[2*p+1][0] = r2; bh[2*p+1][1] = r3;
                ldsm_x4_t(r0, r1, r2, r3, bLoB + off);
                bl[2*p][0] = r0; bl[2*p][1] = r1; bl[2*p+1][0] = r2; bl[2*p+1][1] = r3;
            }
            #pragma unroll
            for (int i = 0; i < 4; i++) {
                unsigned ah[4], al[4];
                unsigned off = (unsigned)(((arow + 16 * i) * ASTR + kb + acol8) * 2);
                ldsm_x4(ah[0], ah[1], ah[2], ah[3], aHiB + off);
                ldsm_x4(al[0], al[1], al[2], al[3], aLoB + off);
                // pass-major: 8 independent accumulator chains between deps
                #pragma unroll
                for (int j = 0; j < 8; j++) mma16816(acc[i][j], ah, bh[j]);
                #pragma unroll
                for (int j = 0; j < 8; j++) mma16816(acc[i][j], ah, bl[j]);
                #pragma unroll
                for (int j = 0; j < 8; j++) mma16816(acc[i][j], al, bh[j]);
            }
        }
        __syncthreads();
    }
}

// ---------------- fused QKV GEMM (+bias, +RoPE for Q/K, BHSD epilogue) ------
__global__ __launch_bounds__(256, 1) void qkv_tc_kernel(
    const float* __restrict__ bQ, const float* __restrict__ bK,
    const float* __restrict__ bV)
{
    extern __shared__ __align__(16) __nv_bfloat16 smg[];
    const int z = blockIdx.z;
    const float* bias = (z == 0) ? bQ : ((z == 1) ? bK : bV);
    const int m0 = blockIdx.y * 256, n0 = blockIdx.x * 128;

    float acc[4][8][4];
    #pragma unroll
    for (int i = 0; i < 4; i++)
        #pragma unroll
        for (int j = 0; j < 8; j++)
            #pragma unroll
            for (int r = 0; r < 4; r++) acc[i][j][r] = 0.f;

    const size_t wz = (size_t)z * HID * HID;
    tc_mainloop(g_xhi, g_xlo, g_Whi + wz, g_Wlo + wz, m0, n0, smg, acc);

    const int tid = threadIdx.x, lane = tid & 31, wid = tid >> 5;
    const int warp_m = wid >> 1, warp_n = wid & 1;
    const int g = lane >> 2, c = lane & 3;
    const int wb = warp_n * 32;
    const int h = blockIdx.x;                 // N-tile == one head
    float* out = (z == 0) ? g_Q : ((z == 1) ? g_K : g_V);

    #pragma unroll
    for (int i = 0; i < 4; i++) {
        #pragma unroll
        for (int rh = 0; rh < 2; rh++) {
            int rm = m0 + warp_m * 64 + 16 * i + g + 8 * rh;
            int bb = rm >> 11, s = rm & (SEQ - 1);
            float* orow = out + ((size_t)(bb * NH + h) * SEQ + s) * HD;
            if (z < 2) {
                #pragma unroll
                for (int j = 0; j < 4; j++) {
                    #pragma unroll
                    for (int d = 0; d < 2; d++) {
                        int reg = rh * 2 + d;
                        int d1  = wb + 8 * j + 2 * c + d;       // < 64
                        float t1 = acc[i][j][reg]     + bias[n0 + d1];
                        float t2 = acc[i][j + 4][reg] + bias[n0 + d1 + 64];
                        float2 cs = g_rope[s * 64 + d1];
                        orow[d1]      = t1 * cs.x - t2 * cs.y;
                        orow[d1 + 64] = t1 * cs.y + t2 * cs.x;
                    }
                }
            } else {
                #pragma unroll
                for (int j = 0; j < 8; j++) {
                    #pragma unroll
                    for (int d = 0; d < 2; d++) {
                        int col = wb + (j & 3) * 8 + (j >> 2) * 64 + 2 * c + d;
                        orow[col] = acc[i][j][rh * 2 + d] + bias[n0 + col];
                    }
                }
            }
        }
    }
}

// ---------------- output projection GEMM (+bias) ----------------------------
__global__ __launch_bounds__(256, 1) void out_tc_kernel(
    const float* __restrict__ bO, float* __restrict__ out)
{
    extern __shared__ __align__(16) __nv_bfloat16 smg[];
    const int m0 = blockIdx.y * 256, n0 = blockIdx.x * 128;

    float acc[4][8][4];
    #pragma unroll
    for (int i = 0; i < 4; i++)
        #pragma unroll
        for (int j = 0; j < 8; j++)
            #pragma unroll
            for (int r = 0; r < 4; r++) acc[i][j][r] = 0.f;

    const size_t wz = (size_t)3 * HID * HID;
    tc_mainloop(g_ahi, g_alo, g_Whi + wz, g_Wlo + wz, m0, n0, smg, acc);

    const int tid = threadIdx.x, lane = tid & 31, wid = tid >> 5;
    const int warp_m = wid >> 1, warp_n = wid & 1;
    const int g = lane >> 2, c = lane & 3;
    const int wb = warp_n * 32;

    #pragma unroll
    for (int i = 0; i < 4; i++) {
        #pragma unroll
        for (int rh = 0; rh < 2; rh++) {
            int rm = m0 + warp_m * 64 + 16 * i + g + 8 * rh;
            #pragma unroll
            for (int j = 0; j < 8; j++) {
                #pragma unroll
                for (int d = 0; d < 2; d++) {
                    int col = n0 + wb + (j & 3) * 8 + (j >> 2) * 64 + 2 * c + d;
                    out[(size_t)rm * HID + col] = acc[i][j][rh * 2 + d] + bO[col];
                }
            }
        }
    }
}

// ---------------- sliding-window flash attention (SIMT, fast exp) ------------
#define QS_OFF 0
#define VS_OFF 8192
#define KS_OFF 16384            // 64 x 33
#define PS_OFF 18496            // 64 x 65
#define ATT_SMEM_BYTES ((18496 + 64*65) * 4)

__global__ __launch_bounds__(256) void attn_kernel(const float* __restrict__ kw) {
    extern __shared__ float sm[];
    float* Qs = sm + QS_OFF;
    float* Vs = sm + VS_OFF;
    float* Ks = sm + KS_OFF;
    float* Ps = sm + PS_OFF;

    const int tid = threadIdx.x;
    const int tx = tid & 15, ty = tid >> 4;
    const int q0 = blockIdx.x * 64;
    const int h  = blockIdx.y, b = blockIdx.z;

    const size_t base = (size_t)(b * NH + h) * SEQ * HD;
    const float* Qg = g_Q + base + (size_t)q0 * HD;
    const float* Kg = g_K + base;
    const float* Vg = g_V + base;

    #pragma unroll
    for (int t = 0; t < 8; t++) {
        int f = tid + t * 256;
        *(float4*)&Qs[f * 4] = *(const float4*)&Qg[f * 4];
    }

    const float mult = 0.08838834764831845f * kw[h];

    float O[4][8];
    #pragma unroll
    for (int i = 0; i < 4; i++)
        #pragma unroll
        for (int j = 0; j < 8; j++) O[i][j] = 0.f;
    float mrow[4], lrow[4];
    #pragma unroll
    for (int i = 0; i < 4; i++) { mrow[i] = -1e30f; lrow[i] = 0.f; }

    const int kt_lo = (q0 >= WIN) ? ((q0 - WIN) >> 6) : 0;
    const int kt_hi = q0 >> 6;

    for (int kt = kt_lo; kt <= kt_hi; kt++) {
        const int k0 = kt * 64;
        __syncthreads();
        #pragma unroll
        for (int t = 0; t < 8; t++) {
            int f = tid + t * 256;
            *(float4*)&Vs[f * 4] = *(const float4*)&Vg[(size_t)k0 * HD + f * 4];
        }

        float S[4][4];
        #pragma unroll
        for (int i = 0; i < 4; i++)
            #pragma unroll
            for (int jj = 0; jj < 4; jj++) S[i][jj] = 0.f;

        #pragma unroll
        for (int dc = 0; dc < 4; dc++) {
            #pragma unroll
            for (int t = 0; t < 2; t++) {
                int f = tid + t * 256;
                int r = f >> 3, c4 = (f & 7) * 4;
                float4 v = *(const float4*)&Kg[(size_t)(k0 + r) * HD + dc * 32 + c4];
                float* kp = &Ks[r * 33 + c4];
                kp[0] = v.x; kp[1] = v.y; kp[2] = v.z; kp[3] = v.w;
            }
            __syncthreads();
            #pragma unroll
            for (int d = 0; d < 32; d++) {
                float ra[4], rb[4];
                #pragma unroll
                for (int i = 0; i < 4; i++)  ra[i]  = Qs[(ty * 4 + i) * HD + dc * 32 + d];
                #pragma unroll
                for (int jj = 0; jj < 4; jj++) rb[jj] = Ks[(tx + 16 * jj) * 33 + d];
                #pragma unroll
                for (int i = 0; i < 4; i++)
                    #pragma unroll
                    for (int jj = 0; jj < 4; jj++)
                        S[i][jj] = fmaf(ra[i], rb[jj], S[i][jj]);
            }
            __syncthreads();
        }

        #pragma unroll
        for (int i = 0; i < 4; i++) {
            int qi = q0 + ty * 4 + i;
            float mloc = -1e30f;
            #pragma unroll
            for (int jj = 0; jj < 4; jj++) {
                int kj = k0 + tx + 16 * jj;
                float sv = S[i][jj] * mult;
                sv = (kj <= qi && kj + WIN >= qi) ? sv : -1e30f;
                S[i][jj] = sv;
                mloc = fmaxf(mloc, sv);
            }
            #pragma unroll
            for (int msk = 8; msk >= 1; msk >>= 1)
                mloc = fmaxf(mloc, __shfl_xor_sync(0xffffffffu, mloc, msk));
            float mnew = fmaxf(mrow[i], mloc);
            float corr = __expf(mrow[i] - mnew);
            float psum = 0.f;
            #pragma unroll
            for (int jj = 0; jj < 4; jj++) {
                float p = __expf(S[i][jj] - mnew);
                Ps[(ty * 4 + i) * 65 + tx + 16 * jj] = p;
                psum += p;
            }
            #pragma unroll
            for (int msk = 8; msk >= 1; msk >>= 1)
                psum += __shfl_xor_sync(0xffffffffu, psum, msk);
            lrow[i] = lrow[i] * corr + psum;
            mrow[i] = mnew;
            #pragma unroll
            for (int j = 0; j < 8; j++) O[i][j] *= corr;
        }
        __syncthreads();

        #pragma unroll 4
        for (int k = 0; k < 64; k++) {
            float rp[4], rv[8];
            #pragma unroll
            for (int i = 0; i < 4; i++) rp[i] = Ps[(ty * 4 + i) * 65 + k];
            #pragma unroll
            for (int j = 0; j < 8; j++) rv[j] = Vs[k * HD + tx + 16 * j];
            #pragma unroll
            for (int i = 0; i < 4; i++)
                #pragma unroll
                for (int j = 0; j < 8; j++)
                    O[i][j] = fmaf(rp[i], rv[j], O[i][j]);
        }
    }

    // epilogue: pre-split bf16 hi/lo for the output GEMM
    #pragma unroll
    for (int i = 0; i < 4; i++) {
        int qi = q0 + ty * 4 + i;
        float inv = 1.f / lrow[i];
        size_t row = ((size_t)b * SEQ + qi) * HID + h * HD;
        #pragma unroll
        for (int j = 0; j < 8; j++) {
            float v = O[i][j] * inv;
            __nv_bfloat16 hh = __float2bfloat16(v);
            __nv_bfloat16 ll = __float2bfloat16(v - __bfloat162float(hh));
            g_ahi[row + tx + 16 * j] = hh;
            g_alo[row + tx + 16 * j] = ll;
        }
    }
}

// ---------------- launch -----------------------------------------------------
extern "C" void kernel_launch(void* const* d_in, const int* in_sizes, int n_in,
                              void* d_out, int out_size) {
    const float* x  = (const float*)d_in[0];
    const float* WQ = (const float*)d_in[1];
    const float* bQ = (const float*)d_in[2];
    const float* WK = (const float*)d_in[3];
    const float* bK = (const float*)d_in[4];
    const float* WV = (const float*)d_in[5];
    const float* bV = (const float*)d_in[6];
    const float* WO = (const float*)d_in[7];
    const float* bO = (const float*)d_in[8];
    const float* kw = (const float*)d_in[9];
    float* out = (float*)d_out;

    static __nv_bfloat16 *xhi = nullptr, *xlo = nullptr, *whi = nullptr, *wlo = nullptr;
    static bool attr_set = false;
    if (!xhi) {
        cudaGetSymbolAddress((void**)&xhi, g_xhi);
        cudaGetSymbolAddress((void**)&xlo, g_xlo);
        cudaGetSymbolAddress((void**)&whi, g_Whi);
        cudaGetSymbolAddress((void**)&wlo, g_Wlo);
    }
    if (!attr_set) {
        cudaFuncSetAttribute(qkv_tc_kernel, cudaFuncAttributeMaxDynamicSharedMemorySize, GEMM_SMEM_BYTES);
        cudaFuncSetAttribute(out_tc_kernel, cudaFuncAttributeMaxDynamicSharedMemorySize, GEMM_SMEM_BYTES);
        cudaFuncSetAttribute(attn_kernel,   cudaFuncAttributeMaxDynamicSharedMemorySize, ATT_SMEM_BYTES);
        attr_set = true;
    }

    rope_tab_kernel<<<(SEQ * 64 + 255) / 256, 256>>>();

    const int n4x = MTOT * HID / 4;
    const int n4w = HID * HID / 4;
    split_kernel<<<(n4x + 255) / 256, 256>>>(x,  xhi, xlo, n4x);
    split_kernel<<<(n4w + 255) / 256, 256>>>(WQ, whi + 0ull * HID * HID, wlo + 0ull * HID * HID, n4w);
    split_kernel<<<(n4w + 255) / 256, 256>>>(WK, whi + 1ull * HID * HID, wlo + 1ull * HID * HID, n4w);
    split_kernel<<<(n4w + 255) / 256, 256>>>(WV, whi + 2ull * HID * HID, wlo + 2ull * HID * HID, n4w);
    split_kernel<<<(n4w + 255) / 256, 256>>>(WO, whi + 3ull * HID * HID, wlo + 3ull * HID * HID, n4w);

    dim3 gq(NH, MTOT / 256, 3);
    qkv_tc_kernel<<<gq, 256, GEMM_SMEM_BYTES>>>(bQ, bK, bV);

    attn_kernel<<<dim3(SEQ / 64, NH, BATCH), 256, ATT_SMEM_BYTES>>>(kw);

    out_tc_kernel<<<dim3(HID / 128, MTOT / 256), 256, GEMM_SMEM_BYTES>>>(bO, out);
}